// round 5
// baseline (speedup 1.0000x reference)
#include <cuda_runtime.h>
#include <cstdint>

// Blur_by_Kernel: per-batch 21x21 depthwise correlation, reflect pad 10.
// B=16, C=3, H=W=768, K=21.
// Strategy: fp32 packed f32x2 FMA (sm_103a FFMA2), smem-tiled 128x128 output
// tile per CTA, 16x4 outputs per thread.

#define SW 148              // smem patch row stride (floats), multiple of 4
#define PATCH (SW * SW)     // 148*148 floats
#define SMEM_FLOATS (PATCH + 441)
#define SMEM_BYTES (SMEM_FLOATS * 4)

typedef unsigned long long ull;

__device__ __forceinline__ ull dup2(float v) {
    ull r;
    asm("mov.b64 %0, {%1, %1};" : "=l"(r) : "f"(v));
    return r;
}

// returns pair (hi(a), lo(b))  -- the 1-element-shifted pair
__device__ __forceinline__ ull mid2(ull a, ull b) {
    ull r;
    asm("{\n\t"
        ".reg .b32 al, ah, bl, bh;\n\t"
        "mov.b64 {al, ah}, %1;\n\t"
        "mov.b64 {bl, bh}, %2;\n\t"
        "mov.b64 %0, {ah, bl};\n\t"
        "}"
        : "=l"(r) : "l"(a), "l"(b));
    return r;
}

__device__ __forceinline__ void ffma2(ull& d, ull a, ull b) {
    asm("fma.rn.f32x2 %0, %1, %2, %0;" : "+l"(d) : "l"(a), "l"(b));
}

__global__ void __launch_bounds__(256, 1)
blur21_kernel(const float* __restrict__ gin_all,
              const float* __restrict__ gker,
              float* __restrict__ gout_all)
{
    extern __shared__ float smem[];
    float* s_in = smem;           // [148*148]
    float* s_k  = smem + PATCH;   // [441]

    const int tid = threadIdx.x;
    const int bc  = blockIdx.z;           // b*3 + c, 0..47
    const int b   = bc / 3;

    const float* gin = gin_all + (size_t)bc * (768 * 768);
    const float* gk  = gker + b * 441;

    const int x0 = blockIdx.x * 128 - 10;
    const int y0 = blockIdx.y * 128 - 10;

    // ---- fill smem patch with reflect indexing ----
    for (int idx = tid; idx < PATCH; idx += 256) {
        int py = idx / SW;
        int px = idx - py * SW;
        int gy = y0 + py;
        gy = (gy < 0) ? -gy : gy;
        gy = (gy > 767) ? (1534 - gy) : gy;
        int gx = x0 + px;
        gx = (gx < 0) ? -gx : gx;
        gx = (gx > 767) ? (1534 - gx) : gx;
        s_in[idx] = gin[gy * 768 + gx];
    }
    for (int idx = tid; idx < 441; idx += 256)
        s_k[idx] = gk[idx];
    __syncthreads();

    // thread -> 16 x-outputs (8 f32x2 pairs) x 4 y-outputs
    const int lx = tid & 7;     // 0..7  -> x block of 16
    const int ly = tid >> 3;    // 0..31 -> y block of 4
    const int xb = lx * 16;

    ull acc[4][8];
#pragma unroll
    for (int iy = 0; iy < 4; ++iy)
#pragma unroll
        for (int p = 0; p < 8; ++p)
            acc[iy][p] = 0ULL;   // bit pattern of (0.0f, 0.0f)

    for (int rr = 0; rr < 24; ++rr) {
        const float* row = s_in + (ly * 4 + rr) * SW + xb;

        // 36 floats -> 18 aligned pairs
        ull rp[18];
#pragma unroll
        for (int c = 0; c < 9; ++c) {
            ulonglong2 v = *reinterpret_cast<const ulonglong2*>(row + c * 4);
            rp[2 * c]     = v.x;
            rp[2 * c + 1] = v.y;
        }
        // shifted pairs: sp[h] = (r[2h+1], r[2h+2])
        ull sp[17];
#pragma unroll
        for (int h = 0; h < 17; ++h)
            sp[h] = mid2(rp[h], rp[h + 1]);

#pragma unroll
        for (int iy = 0; iy < 4; ++iy) {
            const int i = rr - iy;          // kernel row index
            if (i < 0 || i > 20) continue;
            const float* kr = s_k + i * 21;
#pragma unroll
            for (int j = 0; j < 21; ++j) {
                const ull kb = dup2(kr[j]);
                const int h = j >> 1;
                if ((j & 1) == 0) {
                    ffma2(acc[iy][0], rp[h + 0], kb);
                    ffma2(acc[iy][1], rp[h + 1], kb);
                    ffma2(acc[iy][2], rp[h + 2], kb);
                    ffma2(acc[iy][3], rp[h + 3], kb);
                    ffma2(acc[iy][4], rp[h + 4], kb);
                    ffma2(acc[iy][5], rp[h + 5], kb);
                    ffma2(acc[iy][6], rp[h + 6], kb);
                    ffma2(acc[iy][7], rp[h + 7], kb);
                } else {
                    ffma2(acc[iy][0], sp[h + 0], kb);
                    ffma2(acc[iy][1], sp[h + 1], kb);
                    ffma2(acc[iy][2], sp[h + 2], kb);
                    ffma2(acc[iy][3], sp[h + 3], kb);
                    ffma2(acc[iy][4], sp[h + 4], kb);
                    ffma2(acc[iy][5], sp[h + 5], kb);
                    ffma2(acc[iy][6], sp[h + 6], kb);
                    ffma2(acc[iy][7], sp[h + 7], kb);
                }
            }
        }
    }

    // ---- store 16x4 outputs, 16B vector stores ----
    float* gout = gout_all + (size_t)bc * (768 * 768)
                + (size_t)(blockIdx.y * 128 + ly * 4) * 768
                + blockIdx.x * 128 + xb;
#pragma unroll
    for (int iy = 0; iy < 4; ++iy) {
        ulonglong2* o = reinterpret_cast<ulonglong2*>(gout + iy * 768);
        o[0] = make_ulonglong2(acc[iy][0], acc[iy][1]);
        o[1] = make_ulonglong2(acc[iy][2], acc[iy][3]);
        o[2] = make_ulonglong2(acc[iy][4], acc[iy][5]);
        o[3] = make_ulonglong2(acc[iy][6], acc[iy][7]);
    }
}

extern "C" void kernel_launch(void* const* d_in, const int* in_sizes, int n_in,
                              void* d_out, int out_size)
{
    const float* inp = (const float*)d_in[0];   // (16,3,768,768) f32
    const float* ker = (const float*)d_in[1];   // (16,21,21) f32
    float* out = (float*)d_out;                 // (16,3,768,768) f32

    cudaFuncSetAttribute(blur21_kernel,
                         cudaFuncAttributeMaxDynamicSharedMemorySize,
                         SMEM_BYTES);

    dim3 grid(6, 6, 48);   // 768/128 x-tiles, 768/128 y-tiles, 16*3 images
    blur21_kernel<<<grid, 256, SMEM_BYTES>>>(inp, ker, out);
}